// round 4
// baseline (speedup 1.0000x reference)
#include <cuda_runtime.h>
#include <math.h>

#define NN 50000
#define NE 800000
#define C1 128
#define C2 64
#define NBLK ((NN + 255) / 256)   // 196 scan blocks

// ---------------- scratch (static device globals — allocation-free) --------
__device__ float g_h1[(size_t)NN * C1];    // dinv*(x@W1)
__device__ float g_agg1[(size_t)NN * C1];  // layer1 output (post relu)
__device__ float g_h2[(size_t)NN * C2];    // dinv*(agg1@W2)
__device__ float g_dinv[NN];
__device__ int   g_cnt[NN];
__device__ int   g_rowstart[NN + 1];
__device__ int   g_cursor[NN];
__device__ int   g_src[NE];
__device__ int   g_bsum[NBLK];

// ---------------- packed fp32x2 FMA (sm_100+: full-rate fp32 path) ----------
__device__ __forceinline__ void ffma2(unsigned long long& acc,
                                      unsigned long long a, unsigned long long b) {
    asm("fma.rn.f32x2 %0, %1, %2, %0;" : "+l"(acc) : "l"(a), "l"(b));
}
__device__ __forceinline__ unsigned long long dup2(float a) {
    unsigned long long d;
    asm("mov.b64 %0, {%1, %1};" : "=l"(d) : "f"(a));
    return d;
}
__device__ __forceinline__ float2 unpack2(unsigned long long v) {
    float lo, hi;
    asm("mov.b64 {%0, %1}, %2;" : "=f"(lo), "=f"(hi) : "l"(v));
    return make_float2(lo, hi);
}

// ---------------- CSR construction ------------------------------------------
__global__ void k_zero(int* cnt, int n) {
    int i = blockIdx.x * blockDim.x + threadIdx.x;
    if (i < n) cnt[i] = 0;
}

__global__ void k_hist(const int* __restrict__ col, int* cnt, int e) {
    int i = blockIdx.x * blockDim.x + threadIdx.x;
    if (i < e) atomicAdd(&cnt[col[i]], 1);
}

// per-block exclusive scan (256 elems) + block totals
__global__ void k_scan_block(const int* __restrict__ cnt, int* ex, int* bsum, int n) {
    __shared__ int sh[256];
    int i = blockIdx.x * 256 + threadIdx.x;
    int v = (i < n) ? cnt[i] : 0;
    sh[threadIdx.x] = v;
    __syncthreads();
    for (int off = 1; off < 256; off <<= 1) {
        int t = (threadIdx.x >= off) ? sh[threadIdx.x - off] : 0;
        __syncthreads();
        sh[threadIdx.x] += t;
        __syncthreads();
    }
    int inc = sh[threadIdx.x];
    if (i < n) ex[i] = inc - v;          // exclusive within block
    if (threadIdx.x == 255) bsum[blockIdx.x] = inc;
}

// finalize: add cross-block offset (each block reduces bsum[0..b-1] itself),
// copy cursor, compute dinv.
__global__ void k_finalize(int* rowstart, int* cursor, const int* __restrict__ bsum,
                           const int* __restrict__ cnt, float* dinv, int n, int e) {
    __shared__ int sh[256];
    const int b = blockIdx.x;
    const int t = threadIdx.x;
    sh[t] = (t < b && t < NBLK) ? bsum[t] : 0;
    __syncthreads();
    for (int off = 128; off > 0; off >>= 1) {
        if (t < off) sh[t] += sh[t + off];
        __syncthreads();
    }
    int boff = sh[0];
    int i = b * 256 + t;
    if (i < n) {
        int rs = rowstart[i] + boff;
        rowstart[i] = rs;
        cursor[i]   = rs;
        dinv[i]     = rsqrtf((float)cnt[i] + 1.0f);  // +1 self-loop
    }
    if (i == 0) rowstart[n] = e;
}

__global__ void k_fill(const int* __restrict__ rows, const int* __restrict__ cols,
                       int* cursor, int* src, int e) {
    int i = blockIdx.x * blockDim.x + threadIdx.x;
    if (i < e) {
        int p = atomicAdd(&cursor[cols[i]], 1);
        src[p] = rows[i];
    }
}

// ---------------- fused dense transform: Hs = dinv_row * (X @ W) ------------
// BM=128, BK=16 double-buffered, 256 threads, 8x(C/16) thread tile, f32x2 FMAs.
template <int C>
__global__ __launch_bounds__(256)
void k_gemm_fused(const float* __restrict__ X, const float* __restrict__ W,
                  const float* __restrict__ dinv, float* __restrict__ Hs, int n) {
    constexpr int K   = 128;
    constexpr int BM  = 128;
    constexpr int BK  = 16;
    constexpr int TM  = 8;
    constexpr int TN  = C / 16;   // 8 (C=128) / 4 (C=64)
    constexpr int TN2 = TN / 2;   // packed pairs
    constexpr int NT  = K / BK;   // 8 k-tiles

    extern __shared__ float sm[];
    float* Ws = sm;                 // [K][C]
    float* As = sm + K * C;         // 2 x [BK][BM]

    const int tid  = threadIdx.x;
    const int row0 = blockIdx.x * BM;
    const int tr   = tid >> 4;
    const int tc   = tid & 15;

    // load full W into shared (once)
    for (int i = tid; i < K * C / 4; i += 256)
        reinterpret_cast<float4*>(Ws)[i] = reinterpret_cast<const float4*>(W)[i];

    // tile loaders: 512 float4 per tile / 256 threads = 2 each
    const int r0 = (tid + 0)   >> 2, v0 = (tid + 0)   & 3;
    const int r1 = (tid + 256) >> 2, v1 = (tid + 256) & 3;
    float4 xv0, xv1;

    auto loadX = [&](int k0) {
        xv0 = make_float4(0.f, 0.f, 0.f, 0.f);
        xv1 = make_float4(0.f, 0.f, 0.f, 0.f);
        if (row0 + r0 < n)
            xv0 = reinterpret_cast<const float4*>(X + (size_t)(row0 + r0) * K + k0)[v0];
        if (row0 + r1 < n)
            xv1 = reinterpret_cast<const float4*>(X + (size_t)(row0 + r1) * K + k0)[v1];
    };
    auto storeX = [&](int buf) {
        float* A = As + buf * (BK * BM);
        A[(v0 * 4 + 0) * BM + r0] = xv0.x;
        A[(v0 * 4 + 1) * BM + r0] = xv0.y;
        A[(v0 * 4 + 2) * BM + r0] = xv0.z;
        A[(v0 * 4 + 3) * BM + r0] = xv0.w;
        A[(v1 * 4 + 0) * BM + r1] = xv1.x;
        A[(v1 * 4 + 1) * BM + r1] = xv1.y;
        A[(v1 * 4 + 2) * BM + r1] = xv1.z;
        A[(v1 * 4 + 3) * BM + r1] = xv1.w;
    };

    unsigned long long acc[TM][TN2];
#pragma unroll
    for (int i = 0; i < TM; i++)
#pragma unroll
        for (int j = 0; j < TN2; j++) acc[i][j] = 0ull;

    loadX(0);
    storeX(0);
    __syncthreads();

    for (int t = 0; t < NT; t++) {
        const int k0 = t * BK;
        if (t < NT - 1) loadX(k0 + BK);

        const float* A = As + (t & 1) * (BK * BM);
#pragma unroll
        for (int kk = 0; kk < BK; kk++) {
            const float4* ap = reinterpret_cast<const float4*>(A + kk * BM + tr * TM);
            float4 a0 = ap[0], a1 = ap[1];
            float a[TM];
            a[0]=a0.x; a[1]=a0.y; a[2]=a0.z; a[3]=a0.w;
            a[4]=a1.x; a[5]=a1.y; a[6]=a1.z; a[7]=a1.w;

            unsigned long long b[TN2];
            const ulonglong2* bp =
                reinterpret_cast<const ulonglong2*>(Ws + (k0 + kk) * C + tc * TN);
            ulonglong2 bb0 = bp[0];
            b[0] = bb0.x; b[1] = bb0.y;
            if (TN2 == 4) {
                ulonglong2 bb1 = bp[1];
                b[2] = bb1.x; b[3] = bb1.y;
            }
#pragma unroll
            for (int i = 0; i < TM; i++) {
                unsigned long long ad = dup2(a[i]);
#pragma unroll
                for (int j = 0; j < TN2; j++) ffma2(acc[i][j], ad, b[j]);
            }
        }

        if (t < NT - 1) storeX((t + 1) & 1);
        __syncthreads();
    }

    // epilogue: Hs = dinv_row * acc
#pragma unroll
    for (int i = 0; i < TM; i++) {
        int row = row0 + tr * TM + i;
        if (row >= n) break;
        float di = dinv[row];
        float* hr = Hs + (size_t)row * C + tc * TN;
#pragma unroll
        for (int j = 0; j < TN2; j += 2) {
            float2 p0 = unpack2(acc[i][j]);
            float2 p1 = unpack2(acc[i][j + 1]);
            reinterpret_cast<float4*>(hr)[j / 2] =
                make_float4(di * p0.x, di * p0.y, di * p1.x, di * p1.y);
        }
    }
}

// ---------------- CSR gather: out[c] = act(dinv[c]*(Hs[c] + sum Hs[src]) + b)
template <int C, bool RELU>
__global__ void k_gather(const float* __restrict__ Hs, const int* __restrict__ rowstart,
                         const int* __restrict__ src, const float* __restrict__ dinv,
                         const float* __restrict__ bias, float* __restrict__ out, int n) {
    int warp = (blockIdx.x * blockDim.x + threadIdx.x) >> 5;
    int lane = threadIdx.x & 31;
    if (warp >= n) return;
    const int node = warp;

    if (C == 128) {
        const float4* hp = reinterpret_cast<const float4*>(Hs) + (size_t)node * 32 + lane;
        float4 acc = __ldg(hp);  // self-loop term
        int s = rowstart[node], e = rowstart[node + 1];
        for (int j = s; j < e; j++) {
            int r = __ldg(&src[j]);
            float4 v = __ldg(reinterpret_cast<const float4*>(Hs) + (size_t)r * 32 + lane);
            acc.x += v.x; acc.y += v.y; acc.z += v.z; acc.w += v.w;
        }
        float di = dinv[node];
        float4 bv = __ldg(reinterpret_cast<const float4*>(bias) + lane);
        float4 o = make_float4(fmaf(di, acc.x, bv.x), fmaf(di, acc.y, bv.y),
                               fmaf(di, acc.z, bv.z), fmaf(di, acc.w, bv.w));
        if (RELU) {
            o.x = fmaxf(o.x, 0.f); o.y = fmaxf(o.y, 0.f);
            o.z = fmaxf(o.z, 0.f); o.w = fmaxf(o.w, 0.f);
        }
        reinterpret_cast<float4*>(out)[(size_t)node * 32 + lane] = o;
    } else {
        const float2* hp = reinterpret_cast<const float2*>(Hs) + (size_t)node * 32 + lane;
        float2 acc = __ldg(hp);
        int s = rowstart[node], e = rowstart[node + 1];
        for (int j = s; j < e; j++) {
            int r = __ldg(&src[j]);
            float2 v = __ldg(reinterpret_cast<const float2*>(Hs) + (size_t)r * 32 + lane);
            acc.x += v.x; acc.y += v.y;
        }
        float di = dinv[node];
        float2 bv = __ldg(reinterpret_cast<const float2*>(bias) + lane);
        float2 o = make_float2(fmaf(di, acc.x, bv.x), fmaf(di, acc.y, bv.y));
        if (RELU) { o.x = fmaxf(o.x, 0.f); o.y = fmaxf(o.y, 0.f); }
        reinterpret_cast<float2*>(out)[(size_t)node * 32 + lane] = o;
    }
}

// ---------------- launch -----------------------------------------------------
extern "C" void kernel_launch(void* const* d_in, const int* in_sizes, int n_in,
                              void* d_out, int out_size) {
    const float* x  = (const float*)d_in[0];
    const int*   ei = (const int*)d_in[1];   // rows = ei, cols = ei + NE
    const float* W1 = (const float*)d_in[2];
    const float* b1 = (const float*)d_in[3];
    const float* W2 = (const float*)d_in[4];
    const float* b2 = (const float*)d_in[5];
    float* out = (float*)d_out;

    const int* rows = ei;
    const int* cols = ei + NE;

    float *h1, *agg1, *h2, *dinv;
    int *cnt, *rowstart, *cursor, *srcA, *bsum;
    cudaGetSymbolAddress((void**)&h1,       g_h1);
    cudaGetSymbolAddress((void**)&agg1,     g_agg1);
    cudaGetSymbolAddress((void**)&h2,       g_h2);
    cudaGetSymbolAddress((void**)&dinv,     g_dinv);
    cudaGetSymbolAddress((void**)&cnt,      g_cnt);
    cudaGetSymbolAddress((void**)&rowstart, g_rowstart);
    cudaGetSymbolAddress((void**)&cursor,   g_cursor);
    cudaGetSymbolAddress((void**)&srcA,     g_src);
    cudaGetSymbolAddress((void**)&bsum,     g_bsum);

    const int T = 256;
    const int SMEM1 = (128 * C1 + 2 * 16 * 128) * (int)sizeof(float);  // 81920
    const int SMEM2 = (128 * C2 + 2 * 16 * 128) * (int)sizeof(float);  // 49152
    cudaFuncSetAttribute(k_gemm_fused<C1>, cudaFuncAttributeMaxDynamicSharedMemorySize, SMEM1);
    cudaFuncSetAttribute(k_gemm_fused<C2>, cudaFuncAttributeMaxDynamicSharedMemorySize, SMEM2);

    // ---- CSR build ----
    k_zero<<<(NN + T - 1) / T, T>>>(cnt, NN);
    k_hist<<<(NE + T - 1) / T, T>>>(cols, cnt, NE);
    k_scan_block<<<NBLK, 256>>>(cnt, rowstart, bsum, NN);
    k_finalize<<<NBLK, 256>>>(rowstart, cursor, bsum, cnt, dinv, NN, NE);
    k_fill<<<(NE + T - 1) / T, T>>>(rows, cols, cursor, srcA, NE);

    const int GB = (NN + 127) / 128;          // gemm blocks
    const int GW = (NN * 32 + T - 1) / T;     // gather blocks (warp/node)

    // ---- layer 1 ----
    k_gemm_fused<C1><<<GB, T, SMEM1>>>(x, W1, dinv, h1, NN);
    k_gather<C1, true><<<GW, T>>>(h1, rowstart, srcA, dinv, b1, agg1, NN);

    // ---- layer 2 ----
    k_gemm_fused<C2><<<GB, T, SMEM2>>>(agg1, W2, dinv, h2, NN);
    k_gather<C2, false><<<GW, T>>>(h2, rowstart, srcA, dinv, b2, out, NN);
}

// round 5
// speedup vs baseline: 1.0683x; 1.0683x over previous
#include <cuda_runtime.h>
#include <cuda_fp16.h>
#include <math.h>

#define NN 50000
#define NE 800000
#define C1 128
#define C2 64
#define NBLK ((NN + 255) / 256)   // 196 scan blocks

// ---------------- scratch (static device globals — allocation-free) --------
__device__ __half g_h1[(size_t)NN * C1];    // fp16: dinv*(x@W1)
__device__ float  g_agg1[(size_t)NN * C1];  // layer1 output (post relu), fp32
__device__ __half g_h2[(size_t)NN * C2];    // fp16: dinv*(agg1@W2)
__device__ float  g_dinv[NN];
__device__ int    g_cnt[NN];
__device__ int    g_rowstart[NN + 1];
__device__ int    g_cursor[NN];
__device__ int    g_src[NE];
__device__ int    g_bsum[NBLK];

// ---------------- CSR construction ------------------------------------------
__global__ void k_zero(int* cnt, int n) {
    int i = blockIdx.x * blockDim.x + threadIdx.x;
    if (i < n) cnt[i] = 0;
}

__global__ void k_hist(const int* __restrict__ col, int* cnt, int e) {
    int i = blockIdx.x * blockDim.x + threadIdx.x;
    if (i < e) atomicAdd(&cnt[col[i]], 1);
}

__global__ void k_scan_block(const int* __restrict__ cnt, int* ex, int* bsum, int n) {
    __shared__ int sh[256];
    int i = blockIdx.x * 256 + threadIdx.x;
    int v = (i < n) ? cnt[i] : 0;
    sh[threadIdx.x] = v;
    __syncthreads();
    for (int off = 1; off < 256; off <<= 1) {
        int t = (threadIdx.x >= off) ? sh[threadIdx.x - off] : 0;
        __syncthreads();
        sh[threadIdx.x] += t;
        __syncthreads();
    }
    int inc = sh[threadIdx.x];
    if (i < n) ex[i] = inc - v;
    if (threadIdx.x == 255) bsum[blockIdx.x] = inc;
}

__global__ void k_finalize(int* rowstart, int* cursor, const int* __restrict__ bsum,
                           const int* __restrict__ cnt, float* dinv, int n, int e) {
    __shared__ int sh[256];
    const int b = blockIdx.x;
    const int t = threadIdx.x;
    sh[t] = (t < b && t < NBLK) ? bsum[t] : 0;
    __syncthreads();
    for (int off = 128; off > 0; off >>= 1) {
        if (t < off) sh[t] += sh[t + off];
        __syncthreads();
    }
    int boff = sh[0];
    int i = b * 256 + t;
    if (i < n) {
        int rs = rowstart[i] + boff;
        rowstart[i] = rs;
        cursor[i]   = rs;
        dinv[i]     = rsqrtf((float)cnt[i] + 1.0f);
    }
    if (i == 0) rowstart[n] = e;
}

__global__ void k_fill(const int* __restrict__ rows, const int* __restrict__ cols,
                       int* cursor, int* src, int e) {
    int i = blockIdx.x * blockDim.x + threadIdx.x;
    if (i < e) {
        int p = atomicAdd(&cursor[cols[i]], 1);
        src[p] = rows[i];
    }
}

// ---------------- fused dense transform: Hs = fp16( dinv_row * (X @ W) ) ----
// R3-style: BM=128, BK=16 single-buffer, 256 threads, 8x(C/16) tile, scalar FFMA.
template <int C>
__global__ __launch_bounds__(256)
void k_gemm_fused(const float* __restrict__ X, const float* __restrict__ W,
                  const float* __restrict__ dinv, __half* __restrict__ Hs, int n) {
    constexpr int K  = 128;
    constexpr int BM = 128;
    constexpr int BK = 16;
    constexpr int TM = 8;
    constexpr int TN = C / 16;  // 8 for C=128, 4 for C=64

    extern __shared__ float sm[];
    float* Ws = sm;            // [K][C]
    float* As = sm + K * C;    // [BK][BM]

    const int tid  = threadIdx.x;
    const int row0 = blockIdx.x * BM;
    const int tr   = tid >> 4;
    const int tc   = tid & 15;

    for (int i = tid; i < K * C / 4; i += 256)
        reinterpret_cast<float4*>(Ws)[i] = reinterpret_cast<const float4*>(W)[i];

    float acc[TM][TN];
#pragma unroll
    for (int i = 0; i < TM; i++)
#pragma unroll
        for (int j = 0; j < TN; j++) acc[i][j] = 0.0f;

    for (int k0 = 0; k0 < K; k0 += BK) {
        __syncthreads();
#pragma unroll
        for (int l = 0; l < 2; l++) {
            int idx = tid + l * 256;
            int r   = idx >> 2;
            int v   = idx & 3;
            float4 xv = make_float4(0.f, 0.f, 0.f, 0.f);
            if (row0 + r < n)
                xv = reinterpret_cast<const float4*>(X + (size_t)(row0 + r) * K + k0)[v];
            As[(v * 4 + 0) * BM + r] = xv.x;
            As[(v * 4 + 1) * BM + r] = xv.y;
            As[(v * 4 + 2) * BM + r] = xv.z;
            As[(v * 4 + 3) * BM + r] = xv.w;
        }
        __syncthreads();

#pragma unroll
        for (int kk = 0; kk < BK; kk++) {
            float a[TM], b[TN];
            const float4* ap = reinterpret_cast<const float4*>(As + kk * BM + tr * TM);
            float4 a0 = ap[0], a1 = ap[1];
            a[0]=a0.x; a[1]=a0.y; a[2]=a0.z; a[3]=a0.w;
            a[4]=a1.x; a[5]=a1.y; a[6]=a1.z; a[7]=a1.w;
            const float4* bp = reinterpret_cast<const float4*>(Ws + (k0 + kk) * C + tc * TN);
            float4 b0 = bp[0];
            b[0]=b0.x; b[1]=b0.y; b[2]=b0.z; b[3]=b0.w;
            if (TN == 8) {
                float4 b1 = bp[1];
                b[4]=b1.x; b[5]=b1.y; b[6]=b1.z; b[7]=b1.w;
            }
#pragma unroll
            for (int i = 0; i < TM; i++)
#pragma unroll
                for (int j = 0; j < TN; j++)
                    acc[i][j] = fmaf(a[i], b[j], acc[i][j]);
        }
    }

    // epilogue: Hs = fp16(dinv_row * acc)
#pragma unroll
    for (int i = 0; i < TM; i++) {
        int row = row0 + tr * TM + i;
        if (row >= n) break;
        float di = dinv[row];
        __half* hr = Hs + (size_t)row * C + tc * TN;
        __half2 hpk[TN / 2];
#pragma unroll
        for (int j = 0; j < TN; j += 2)
            hpk[j / 2] = __float22half2_rn(make_float2(di * acc[i][j], di * acc[i][j + 1]));
        if (TN == 8)
            *reinterpret_cast<uint4*>(hr) = *reinterpret_cast<uint4*>(hpk);
        else
            *reinterpret_cast<uint2*>(hr) = *reinterpret_cast<uint2*>(hpk);
    }
}

// ---------------- CSR gather (fp16 Hs, shfl-batched indices) ----------------
// out[c] = act(dinv[c]*(Hs[c] + sum Hs[src]) + b)
// warp per node. C=128: lane holds 4 ch (uint2); C=64: lane holds 2 ch (half2).
template <int C, bool RELU>
__global__ void k_gather(const __half* __restrict__ Hs, const int* __restrict__ rowstart,
                         const int* __restrict__ src, const float* __restrict__ dinv,
                         const float* __restrict__ bias, float* __restrict__ out, int n) {
    int warp = (blockIdx.x * blockDim.x + threadIdx.x) >> 5;
    int lane = threadIdx.x & 31;
    if (warp >= n) return;
    const int node = warp;
    const int s = rowstart[node];
    const int deg = rowstart[node + 1] - s;

    if (C == 128) {
        // self-loop term
        uint2 hv = __ldg(reinterpret_cast<const uint2*>(Hs + (size_t)node * 128) + lane);
        float2 p0 = __half22float2(*reinterpret_cast<__half2*>(&hv.x));
        float2 p1 = __half22float2(*reinterpret_cast<__half2*>(&hv.y));
        float4 acc = make_float4(p0.x, p0.y, p1.x, p1.y);

        for (int base = 0; base < deg; base += 32) {
            int m = min(32, deg - base);
            int myidx = (base + lane < deg) ? __ldg(&src[s + base + lane]) : 0;
            for (int k = 0; k < m; k++) {
                int r = __shfl_sync(0xffffffffu, myidx, k);
                uint2 v = __ldg(reinterpret_cast<const uint2*>(Hs + (size_t)r * 128) + lane);
                float2 q0 = __half22float2(*reinterpret_cast<__half2*>(&v.x));
                float2 q1 = __half22float2(*reinterpret_cast<__half2*>(&v.y));
                acc.x += q0.x; acc.y += q0.y; acc.z += q1.x; acc.w += q1.y;
            }
        }
        float di = dinv[node];
        float4 bv = __ldg(reinterpret_cast<const float4*>(bias) + lane);
        float4 o = make_float4(fmaf(di, acc.x, bv.x), fmaf(di, acc.y, bv.y),
                               fmaf(di, acc.z, bv.z), fmaf(di, acc.w, bv.w));
        if (RELU) {
            o.x = fmaxf(o.x, 0.f); o.y = fmaxf(o.y, 0.f);
            o.z = fmaxf(o.z, 0.f); o.w = fmaxf(o.w, 0.f);
        }
        reinterpret_cast<float4*>(out)[(size_t)node * 32 + lane] = o;
    } else {
        unsigned hv = __ldg(reinterpret_cast<const unsigned*>(Hs + (size_t)node * 64) + lane);
        float2 acc = __half22float2(*reinterpret_cast<__half2*>(&hv));

        for (int base = 0; base < deg; base += 32) {
            int m = min(32, deg - base);
            int myidx = (base + lane < deg) ? __ldg(&src[s + base + lane]) : 0;
            for (int k = 0; k < m; k++) {
                int r = __shfl_sync(0xffffffffu, myidx, k);
                unsigned v = __ldg(reinterpret_cast<const unsigned*>(Hs + (size_t)r * 64) + lane);
                float2 q = __half22float2(*reinterpret_cast<__half2*>(&v));
                acc.x += q.x; acc.y += q.y;
            }
        }
        float di = dinv[node];
        float2 bv = __ldg(reinterpret_cast<const float2*>(bias) + lane);
        float2 o = make_float2(fmaf(di, acc.x, bv.x), fmaf(di, acc.y, bv.y));
        if (RELU) { o.x = fmaxf(o.x, 0.f); o.y = fmaxf(o.y, 0.f); }
        reinterpret_cast<float2*>(out)[(size_t)node * 32 + lane] = o;
    }
}

// ---------------- launch -----------------------------------------------------
extern "C" void kernel_launch(void* const* d_in, const int* in_sizes, int n_in,
                              void* d_out, int out_size) {
    const float* x  = (const float*)d_in[0];
    const int*   ei = (const int*)d_in[1];   // rows = ei, cols = ei + NE
    const float* W1 = (const float*)d_in[2];
    const float* b1 = (const float*)d_in[3];
    const float* W2 = (const float*)d_in[4];
    const float* b2 = (const float*)d_in[5];
    float* out = (float*)d_out;

    const int* rows = ei;
    const int* cols = ei + NE;

    __half *h1, *h2;
    float *agg1, *dinv;
    int *cnt, *rowstart, *cursor, *srcA, *bsum;
    cudaGetSymbolAddress((void**)&h1,       g_h1);
    cudaGetSymbolAddress((void**)&agg1,     g_agg1);
    cudaGetSymbolAddress((void**)&h2,       g_h2);
    cudaGetSymbolAddress((void**)&dinv,     g_dinv);
    cudaGetSymbolAddress((void**)&cnt,      g_cnt);
    cudaGetSymbolAddress((void**)&rowstart, g_rowstart);
    cudaGetSymbolAddress((void**)&cursor,   g_cursor);
    cudaGetSymbolAddress((void**)&srcA,     g_src);
    cudaGetSymbolAddress((void**)&bsum,     g_bsum);

    const int T = 256;
    const int SMEM1 = (128 * C1 + 16 * 128) * (int)sizeof(float);  // 73728
    const int SMEM2 = (128 * C2 + 16 * 128) * (int)sizeof(float);  // 40960
    cudaFuncSetAttribute(k_gemm_fused<C1>, cudaFuncAttributeMaxDynamicSharedMemorySize, SMEM1);
    cudaFuncSetAttribute(k_gemm_fused<C2>, cudaFuncAttributeMaxDynamicSharedMemorySize, SMEM2);

    // ---- CSR build ----
    k_zero<<<(NN + T - 1) / T, T>>>(cnt, NN);
    k_hist<<<(NE + T - 1) / T, T>>>(cols, cnt, NE);
    k_scan_block<<<NBLK, 256>>>(cnt, rowstart, bsum, NN);
    k_finalize<<<NBLK, 256>>>(rowstart, cursor, bsum, cnt, dinv, NN, NE);
    k_fill<<<(NE + T - 1) / T, T>>>(rows, cols, cursor, srcA, NE);

    const int GB = (NN + 127) / 128;          // gemm blocks
    const int GW = (NN * 32 + T - 1) / T;     // gather blocks (warp/node)

    // ---- layer 1 ----
    k_gemm_fused<C1><<<GB, T, SMEM1>>>(x, W1, dinv, h1, NN);
    k_gather<C1, true><<<GW, T>>>(h1, rowstart, srcA, dinv, b1, agg1, NN);

    // ---- layer 2 ----
    k_gemm_fused<C2><<<GB, T, SMEM2>>>(agg1, W2, dinv, h2, NN);
    k_gather<C2, false><<<GW, T>>>(h2, rowstart, srcA, dinv, b2, out, NN);
}

// round 6
// speedup vs baseline: 1.2358x; 1.1568x over previous
#include <cuda_runtime.h>
#include <cuda_fp16.h>
#include <math.h>

#define NN 50000
#define NE 800000
#define C1 128
#define C2 64
#define NBLK ((NN + 255) / 256)   // 196 scan blocks

// ---------------- scratch (static device globals — allocation-free) --------
__device__ __half g_h1[(size_t)NN * C1];    // fp16: dinv*(x@W1)
__device__ float  g_agg1[(size_t)NN * C1];  // layer1 output (post relu), fp32
__device__ __half g_h2[(size_t)NN * C2];    // fp16: dinv*(agg1@W2)
__device__ float  g_dinv[NN];
__device__ int    g_cnt[NN];
__device__ int    g_rowstart[NN + 1];
__device__ int    g_cursor[NN];
__device__ int    g_src[NE];
__device__ int    g_bsum[NBLK];

// ---------------- tf32 helpers ----------------------------------------------
__device__ __forceinline__ unsigned f2tf32(float f) {
    unsigned r;
    asm("cvt.rna.tf32.f32 %0, %1;" : "=r"(r) : "f"(f));
    return r;
}

__device__ __forceinline__ void mma_tf32(float* d, const unsigned* a, const unsigned* b) {
    asm volatile(
        "mma.sync.aligned.m16n8k8.row.col.f32.tf32.tf32.f32 "
        "{%0,%1,%2,%3}, {%4,%5,%6,%7}, {%8,%9}, {%0,%1,%2,%3};"
        : "+f"(d[0]), "+f"(d[1]), "+f"(d[2]), "+f"(d[3])
        : "r"(a[0]), "r"(a[1]), "r"(a[2]), "r"(a[3]), "r"(b[0]), "r"(b[1]));
}

// ---------------- CSR construction ------------------------------------------
__global__ void k_zero(int* cnt, int n) {
    int i = blockIdx.x * blockDim.x + threadIdx.x;
    if (i < n) cnt[i] = 0;
}

__global__ void k_hist(const int* __restrict__ col, int* cnt, int e) {
    int i = blockIdx.x * blockDim.x + threadIdx.x;
    if (i < e) atomicAdd(&cnt[col[i]], 1);
}

__global__ void k_scan_block(const int* __restrict__ cnt, int* ex, int* bsum, int n) {
    __shared__ int sh[256];
    int i = blockIdx.x * 256 + threadIdx.x;
    int v = (i < n) ? cnt[i] : 0;
    sh[threadIdx.x] = v;
    __syncthreads();
    for (int off = 1; off < 256; off <<= 1) {
        int t = (threadIdx.x >= off) ? sh[threadIdx.x - off] : 0;
        __syncthreads();
        sh[threadIdx.x] += t;
        __syncthreads();
    }
    int inc = sh[threadIdx.x];
    if (i < n) ex[i] = inc - v;
    if (threadIdx.x == 255) bsum[blockIdx.x] = inc;
}

__global__ void k_finalize(int* rowstart, int* cursor, const int* __restrict__ bsum,
                           const int* __restrict__ cnt, float* dinv, int n, int e) {
    __shared__ int sh[256];
    const int b = blockIdx.x;
    const int t = threadIdx.x;
    sh[t] = (t < b && t < NBLK) ? bsum[t] : 0;
    __syncthreads();
    for (int off = 128; off > 0; off >>= 1) {
        if (t < off) sh[t] += sh[t + off];
        __syncthreads();
    }
    int boff = sh[0];
    int i = b * 256 + t;
    if (i < n) {
        int rs = rowstart[i] + boff;
        rowstart[i] = rs;
        cursor[i]   = rs;
        dinv[i]     = rsqrtf((float)cnt[i] + 1.0f);
    }
    if (i == 0) rowstart[n] = e;
}

__global__ void k_fill(const int* __restrict__ rows, const int* __restrict__ cols,
                       int* cursor, int* src, int e) {
    int i = blockIdx.x * blockDim.x + threadIdx.x;
    if (i < e) {
        int p = atomicAdd(&cursor[cols[i]], 1);
        src[p] = rows[i];
    }
}

// ---------------- tensor-core transform: Hs = fp16(dinv_row * (X @ W)) ------
// TF32 mma.sync m16n8k8. One CTA: 128 rows x full C. 8 warps (4M x 2N).
// X tile and tf32 W staged in padded smem (conflict-free fragment loads).
template <int C>
__global__ __launch_bounds__(256)
void k_gemm_tc(const float* __restrict__ X, const float* __restrict__ W,
               const float* __restrict__ dinv, __half* __restrict__ Hs, int n) {
    constexpr int K  = 128;
    constexpr int BM = 128;
    constexpr int XP = 132;       // X pitch: XP%32==4 -> A-frag banks 4g+t distinct
    constexpr int WP = C + 8;     // W pitch: WP%32==8 -> B-frag banks 8t+g distinct
    constexpr int WN = C / 2;     // warp N tile (64 / 32)
    constexpr int NF = WN / 8;    // n8 fragments per warp (8 / 4)

    extern __shared__ float sm[];
    float* Xs  = sm;              // [BM][XP]
    float* Wsm = sm + BM * XP;    // [K][WP]

    const int tid  = threadIdx.x;
    const int wid  = tid >> 5;
    const int lane = tid & 31;
    const int wm   = wid >> 1;    // 0..3
    const int wn   = wid & 1;     // 0..1
    const int row0 = blockIdx.x * BM;
    const int g    = lane >> 2;   // 0..7
    const int t    = lane & 3;    // 0..3

    // stage W (tf32-converted)
    for (int i = tid; i < K * (C / 4); i += 256) {
        int r = i / (C / 4), v = i % (C / 4);
        float4 w = __ldg(reinterpret_cast<const float4*>(W + (size_t)r * C) + v);
        float* dst = Wsm + r * WP + v * 4;
        dst[0] = __uint_as_float(f2tf32(w.x));
        dst[1] = __uint_as_float(f2tf32(w.y));
        dst[2] = __uint_as_float(f2tf32(w.z));
        dst[3] = __uint_as_float(f2tf32(w.w));
    }
    // stage X tile (tf32-converted); 128 rows x 32 float4
    for (int i = tid; i < BM * 32; i += 256) {
        int r = i >> 5, v = i & 31;
        float4 xv = make_float4(0.f, 0.f, 0.f, 0.f);
        if (row0 + r < n)
            xv = __ldg(reinterpret_cast<const float4*>(X + (size_t)(row0 + r) * K) + v);
        float* dst = Xs + r * XP + v * 4;
        dst[0] = __uint_as_float(f2tf32(xv.x));
        dst[1] = __uint_as_float(f2tf32(xv.y));
        dst[2] = __uint_as_float(f2tf32(xv.z));
        dst[3] = __uint_as_float(f2tf32(xv.w));
    }
    __syncthreads();

    float acc[2][NF][4];
#pragma unroll
    for (int mi = 0; mi < 2; mi++)
#pragma unroll
        for (int nf = 0; nf < NF; nf++)
#pragma unroll
            for (int q = 0; q < 4; q++) acc[mi][nf][q] = 0.0f;

#pragma unroll
    for (int k0 = 0; k0 < K; k0 += 8) {
        unsigned a[2][4];
#pragma unroll
        for (int mi = 0; mi < 2; mi++) {
            int r = wm * 32 + mi * 16 + g;
            a[mi][0] = __float_as_uint(Xs[r * XP + k0 + t]);
            a[mi][1] = __float_as_uint(Xs[(r + 8) * XP + k0 + t]);
            a[mi][2] = __float_as_uint(Xs[r * XP + k0 + t + 4]);
            a[mi][3] = __float_as_uint(Xs[(r + 8) * XP + k0 + t + 4]);
        }
        unsigned b[NF][2];
#pragma unroll
        for (int nf = 0; nf < NF; nf++) {
            int c = wn * WN + nf * 8 + g;
            b[nf][0] = __float_as_uint(Wsm[(k0 + t) * WP + c]);
            b[nf][1] = __float_as_uint(Wsm[(k0 + t + 4) * WP + c]);
        }
#pragma unroll
        for (int mi = 0; mi < 2; mi++)
#pragma unroll
            for (int nf = 0; nf < NF; nf++)
                mma_tf32(acc[mi][nf], a[mi], b[nf]);
    }

    // epilogue: Hs = fp16(dinv_row * acc). c0,c1 = cols (2t, 2t+1) row g;
    // c2,c3 = same cols row g+8.
#pragma unroll
    for (int mi = 0; mi < 2; mi++) {
        int rA = row0 + wm * 32 + mi * 16 + g;
        int rB = rA + 8;
        float dA = (rA < n) ? dinv[rA] : 0.f;
        float dB = (rB < n) ? dinv[rB] : 0.f;
#pragma unroll
        for (int nf = 0; nf < NF; nf++) {
            int c = wn * WN + nf * 8 + 2 * t;
            if (rA < n) {
                __half2 hA = __float22half2_rn(
                    make_float2(dA * acc[mi][nf][0], dA * acc[mi][nf][1]));
                *reinterpret_cast<__half2*>(Hs + (size_t)rA * C + c) = hA;
            }
            if (rB < n) {
                __half2 hB = __float22half2_rn(
                    make_float2(dB * acc[mi][nf][2], dB * acc[mi][nf][3]));
                *reinterpret_cast<__half2*>(Hs + (size_t)rB * C + c) = hB;
            }
        }
    }
}

// ---------------- CSR gather (fp16 Hs, shfl-batched indices) ----------------
template <int C, bool RELU>
__global__ void k_gather(const __half* __restrict__ Hs, const int* __restrict__ rowstart,
                         const int* __restrict__ src, const float* __restrict__ dinv,
                         const float* __restrict__ bias, float* __restrict__ out, int n) {
    int warp = (blockIdx.x * blockDim.x + threadIdx.x) >> 5;
    int lane = threadIdx.x & 31;
    if (warp >= n) return;
    const int node = warp;
    const int s = rowstart[node];
    const int deg = rowstart[node + 1] - s;

    if (C == 128) {
        uint2 hv = __ldg(reinterpret_cast<const uint2*>(Hs + (size_t)node * 128) + lane);
        float2 p0 = __half22float2(*reinterpret_cast<__half2*>(&hv.x));
        float2 p1 = __half22float2(*reinterpret_cast<__half2*>(&hv.y));
        float4 acc = make_float4(p0.x, p0.y, p1.x, p1.y);

        for (int base = 0; base < deg; base += 32) {
            int m = min(32, deg - base);
            int myidx = (base + lane < deg) ? __ldg(&src[s + base + lane]) : 0;
            for (int k = 0; k < m; k++) {
                int r = __shfl_sync(0xffffffffu, myidx, k);
                uint2 v = __ldg(reinterpret_cast<const uint2*>(Hs + (size_t)r * 128) + lane);
                float2 q0 = __half22float2(*reinterpret_cast<__half2*>(&v.x));
                float2 q1 = __half22float2(*reinterpret_cast<__half2*>(&v.y));
                acc.x += q0.x; acc.y += q0.y; acc.z += q1.x; acc.w += q1.y;
            }
        }
        float di = dinv[node];
        float4 bv = __ldg(reinterpret_cast<const float4*>(bias) + lane);
        float4 o = make_float4(fmaf(di, acc.x, bv.x), fmaf(di, acc.y, bv.y),
                               fmaf(di, acc.z, bv.z), fmaf(di, acc.w, bv.w));
        if (RELU) {
            o.x = fmaxf(o.x, 0.f); o.y = fmaxf(o.y, 0.f);
            o.z = fmaxf(o.z, 0.f); o.w = fmaxf(o.w, 0.f);
        }
        reinterpret_cast<float4*>(out)[(size_t)node * 32 + lane] = o;
    } else {
        unsigned hv = __ldg(reinterpret_cast<const unsigned*>(Hs + (size_t)node * 64) + lane);
        float2 acc = __half22float2(*reinterpret_cast<__half2*>(&hv));

        for (int base = 0; base < deg; base += 32) {
            int m = min(32, deg - base);
            int myidx = (base + lane < deg) ? __ldg(&src[s + base + lane]) : 0;
            for (int k = 0; k < m; k++) {
                int r = __shfl_sync(0xffffffffu, myidx, k);
                unsigned v = __ldg(reinterpret_cast<const unsigned*>(Hs + (size_t)r * 64) + lane);
                float2 q = __half22float2(*reinterpret_cast<__half2*>(&v));
                acc.x += q.x; acc.y += q.y;
            }
        }
        float di = dinv[node];
        float2 bv = __ldg(reinterpret_cast<const float2*>(bias) + lane);
        float2 o = make_float2(fmaf(di, acc.x, bv.x), fmaf(di, acc.y, bv.y));
        if (RELU) { o.x = fmaxf(o.x, 0.f); o.y = fmaxf(o.y, 0.f); }
        reinterpret_cast<float2*>(out)[(size_t)node * 32 + lane] = o;
    }
}

// ---------------- launch -----------------------------------------------------
extern "C" void kernel_launch(void* const* d_in, const int* in_sizes, int n_in,
                              void* d_out, int out_size) {
    const float* x  = (const float*)d_in[0];
    const int*   ei = (const int*)d_in[1];   // rows = ei, cols = ei + NE
    const float* W1 = (const float*)d_in[2];
    const float* b1 = (const float*)d_in[3];
    const float* W2 = (const float*)d_in[4];
    const float* b2 = (const float*)d_in[5];
    float* out = (float*)d_out;

    const int* rows = ei;
    const int* cols = ei + NE;

    __half *h1, *h2;
    float *agg1, *dinv;
    int *cnt, *rowstart, *cursor, *srcA, *bsum;
    cudaGetSymbolAddress((void**)&h1,       g_h1);
    cudaGetSymbolAddress((void**)&agg1,     g_agg1);
    cudaGetSymbolAddress((void**)&h2,       g_h2);
    cudaGetSymbolAddress((void**)&dinv,     g_dinv);
    cudaGetSymbolAddress((void**)&cnt,      g_cnt);
    cudaGetSymbolAddress((void**)&rowstart, g_rowstart);
    cudaGetSymbolAddress((void**)&cursor,   g_cursor);
    cudaGetSymbolAddress((void**)&srcA,     g_src);
    cudaGetSymbolAddress((void**)&bsum,     g_bsum);

    const int T = 256;
    const int SMEM1 = (128 * 132 + 128 * (C1 + 8)) * (int)sizeof(float);  // 137216
    const int SMEM2 = (128 * 132 + 128 * (C2 + 8)) * (int)sizeof(float);  // 104448
    cudaFuncSetAttribute(k_gemm_tc<C1>, cudaFuncAttributeMaxDynamicSharedMemorySize, SMEM1);
    cudaFuncSetAttribute(k_gemm_tc<C2>, cudaFuncAttributeMaxDynamicSharedMemorySize, SMEM2);

    // ---- CSR build ----
    k_zero<<<(NN + T - 1) / T, T>>>(cnt, NN);
    k_hist<<<(NE + T - 1) / T, T>>>(cols, cnt, NE);
    k_scan_block<<<NBLK, 256>>>(cnt, rowstart, bsum, NN);
    k_finalize<<<NBLK, 256>>>(rowstart, cursor, bsum, cnt, dinv, NN, NE);
    k_fill<<<(NE + T - 1) / T, T>>>(rows, cols, cursor, srcA, NE);

    const int GB = (NN + 127) / 128;          // gemm blocks
    const int GW = (NN * 32 + T - 1) / T;     // gather blocks (warp/node)

    // ---- layer 1 ----
    k_gemm_tc<C1><<<GB, T, SMEM1>>>(x, W1, dinv, h1, NN);
    k_gather<C1, true><<<GW, T>>>(h1, rowstart, srcA, dinv, b1, agg1, NN);

    // ---- layer 2 ----
    k_gemm_tc<C2><<<GB, T, SMEM2>>>(agg1, W2, dinv, h2, NN);
    k_gather<C2, false><<<GW, T>>>(h2, rowstart, srcA, dinv, b2, out, NN);
}